// round 7
// baseline (speedup 1.0000x reference)
#include <cuda_runtime.h>
#include <cuda_fp16.h>
#include <cstdint>

#define BATCH 8
#define SEQ   4096
#define DIM   1024
#define RNK   64
#define KB    64
#define NIT   (SEQ/KB)

// ---------------- global scratch ----------------
__device__ __align__(16) __half g_P[BATCH * SEQ * RNK];
__device__ __align__(16) __half g_xh[(size_t)BATCH * SEQ * DIM];
__device__ __align__(16) __half g_Qt[RNK * DIM];          // Q^T * sqrt(log2e)/32, fp16
__device__ __align__(16) float  g_csum[BATCH * DIM];
__device__ __align__(16) float  g_cpart[8][BATCH * DIM];

// ---------------- helpers ----------------
__device__ __forceinline__ uint32_t smem_u32(const void* p) {
    uint32_t a;
    asm("{ .reg .u64 t; cvta.to.shared.u64 t, %1; cvt.u32.u64 %0, t; }" : "=r"(a) : "l"(p));
    return a;
}
__device__ __forceinline__ void ldsm4(uint32_t* r, uint32_t a) {
    asm volatile("ldmatrix.sync.aligned.m8n8.x4.shared.b16 {%0,%1,%2,%3}, [%4];"
        : "=r"(r[0]), "=r"(r[1]), "=r"(r[2]), "=r"(r[3]) : "r"(a));
}
__device__ __forceinline__ void ldsm4t(uint32_t* r, uint32_t a) {
    asm volatile("ldmatrix.sync.aligned.m8n8.x4.trans.shared.b16 {%0,%1,%2,%3}, [%4];"
        : "=r"(r[0]), "=r"(r[1]), "=r"(r[2]), "=r"(r[3]) : "r"(a));
}
__device__ __forceinline__ void mma16816(float* d, const uint32_t* a, const uint32_t* b) {
    asm volatile(
        "mma.sync.aligned.m16n8k16.row.col.f32.f16.f16.f32 "
        "{%0,%1,%2,%3}, {%4,%5,%6,%7}, {%8,%9}, {%0,%1,%2,%3};"
        : "+f"(d[0]), "+f"(d[1]), "+f"(d[2]), "+f"(d[3])
        : "r"(a[0]), "r"(a[1]), "r"(a[2]), "r"(a[3]), "r"(b[0]), "r"(b[1]));
}
#define CP16(dst, src) \
    asm volatile("cp.async.cg.shared.global [%0], [%1], 16;" :: "r"(dst), "l"(src))
#define CP_COMMIT() asm volatile("cp.async.commit_group;" ::: "memory")
#define CP_WAIT0()  asm volatile("cp.async.wait_group 0;" ::: "memory")
#define CP_WAIT1()  asm volatile("cp.async.wait_group 1;" ::: "memory")
#define BAR_SYNC(id)   asm volatile("bar.sync %0, 256;"   :: "r"(id) : "memory")
#define BAR_ARRIVE(id) asm volatile("bar.arrive %0, 256;" :: "r"(id) : "memory")
// barrier ids: 1,2 = READY[buf]; 3,4 = FREE[buf]

__device__ __forceinline__ uint32_t packh(float a, float b) {
    __half2 h = __floats2half2_rn(a, b);
    return *(uint32_t*)&h;
}
__device__ __forceinline__ float ex2(float s) {
    float p;
    asm("ex2.approx.f32 %0, %1;" : "=f"(p) : "f"(s));
    return p;
}

// ---------------------------------------------------------------------------
// cvt: x fp32 -> fp16 (streaming)
// ---------------------------------------------------------------------------
__global__ __launch_bounds__(256)
void cvt_kernel(const float* __restrict__ x) {
    size_t idx = (size_t)blockIdx.x * 256 + threadIdx.x;
    float4 v = ((const float4*)x)[idx];
    ((uint2*)g_xh)[idx] = make_uint2(packh(v.x, v.y), packh(v.z, v.w));
}

// ---------------------------------------------------------------------------
// qprep: Q -> g_Qt [64 n][1024 k] fp16, scaled by sqrt(log2 e)/32
// ---------------------------------------------------------------------------
__global__ __launch_bounds__(256)
void qprep_kernel(const float* __restrict__ Q) {
    __shared__ float ts[64][65];
    const int t = threadIdx.x;
    const int k0 = blockIdx.x * 64;
    const int r = t >> 2, cb = (t & 3) << 4;
    const float SC = 0.037535075274576556f;
    const float* qp = Q + (size_t)(k0 + r) * RNK + cb;
#pragma unroll
    for (int m = 0; m < 4; m++) {
        float4 v = *(const float4*)(qp + 4 * m);
        ts[r][cb + 4 * m + 0] = v.x * SC;
        ts[r][cb + 4 * m + 1] = v.y * SC;
        ts[r][cb + 4 * m + 2] = v.z * SC;
        ts[r][cb + 4 * m + 3] = v.w * SC;
    }
    __syncthreads();
    __half* o = g_Qt + (size_t)r * DIM + k0 + cb;
#pragma unroll
    for (int m = 0; m < 2; m++) {
        uint32_t w[4];
#pragma unroll
        for (int p = 0; p < 4; p++)
            w[p] = packh(ts[cb + 8 * m + 2 * p][r], ts[cb + 8 * m + 2 * p + 1][r]);
        *(uint4*)(o + 8 * m) = make_uint4(w[0], w[1], w[2], w[3]);
    }
}

// ---------------------------------------------------------------------------
// projH: P = x_h @ Qt^T via HMMA
// ---------------------------------------------------------------------------
#define POFF_X 0
#define POFF_Q 32768
#define PSM_TOTAL 49152

__global__ __launch_bounds__(256, 2)
void projH_kernel() {
    extern __shared__ char sm[];
    const uint32_t smb = smem_u32(sm);
    const int t = threadIdx.x;
    const int warp = t >> 5, lane = t & 31;
    const int row0 = blockIdx.x * 128;
    const int q0 = warp * 16;
    const int tg = lane & 3, g = lane >> 2;
    const int i7 = lane & 7, grp = lane >> 3;

    {
#pragma unroll
        for (int m = 0; m < 4; m++) {
            int idx = t + 256 * m;
            int row = idx >> 3, ch = idx & 7;
            uint32_t dsw = row * 128 + (((uint32_t)(ch ^ (row & 7))) << 4);
            CP16(smb + POFF_X + dsw, g_xh + (size_t)(row0 + row) * DIM + ch * 8);
        }
#pragma unroll
        for (int m = 0; m < 2; m++) {
            int idx = t + 256 * m;
            int row = idx >> 3, ch = idx & 7;
            uint32_t dsw = row * 128 + (((uint32_t)(ch ^ (row & 7))) << 4);
            CP16(smb + POFF_Q + dsw, g_Qt + (size_t)row * DIM + ch * 8);
        }
        CP_COMMIT();
    }

    const uint32_t rowA = q0 + i7 + ((grp & 1) << 3);
    const uint32_t cselA = grp >> 1;
    const uint32_t rowB = i7 + ((grp >> 1) << 3);
    const uint32_t cselB = grp & 1;

    float S[8][4];
#pragma unroll
    for (int n = 0; n < 8; n++)
#pragma unroll
        for (int e = 0; e < 4; e++) S[n][e] = 0.f;

    for (int c = 0; c < 16; c++) {
        const int buf = c & 1;
        CP_WAIT0();
        __syncthreads();
        if (c + 1 < 16) {
            const int kc = (c + 1) * 64;
            const int bo = buf ^ 1;
#pragma unroll
            for (int m = 0; m < 4; m++) {
                int idx = t + 256 * m;
                int row = idx >> 3, ch = idx & 7;
                uint32_t dsw = row * 128 + (((uint32_t)(ch ^ (row & 7))) << 4);
                CP16(smb + POFF_X + bo * 16384 + dsw,
                     g_xh + (size_t)(row0 + row) * DIM + kc + ch * 8);
            }
#pragma unroll
            for (int m = 0; m < 2; m++) {
                int idx = t + 256 * m;
                int row = idx >> 3, ch = idx & 7;
                uint32_t dsw = row * 128 + (((uint32_t)(ch ^ (row & 7))) << 4);
                CP16(smb + POFF_Q + bo * 8192 + dsw,
                     g_Qt + (size_t)row * DIM + kc + ch * 8);
            }
            CP_COMMIT();
        }
        const uint32_t xb = smb + POFF_X + buf * 16384;
        const uint32_t qb = smb + POFF_Q + buf * 8192;
#pragma unroll
        for (int kt = 0; kt < 4; kt++) {
            uint32_t ah[4];
            ldsm4(ah, xb + rowA * 128 + ((((kt << 1) + cselA) ^ i7) << 4));
#pragma unroll
            for (int np = 0; np < 4; np++) {
                uint32_t bh[4];
                ldsm4(bh, qb + ((np << 4) + rowB) * 128
                          + ((((kt << 1) + cselB) ^ i7) << 4));
                mma16816(S[2 * np],     ah, bh + 0);
                mma16816(S[2 * np + 1], ah, bh + 2);
            }
        }
        __syncthreads();
    }

    const int row = row0 + q0 + g;
#pragma unroll
    for (int j = 0; j < 8; j++) {
        const int nb = (j >> 1) * 16 + (j & 1) * 8;
        *(uint32_t*)&g_P[(size_t)row * RNK + nb + 2 * tg] = packh(S[j][0], S[j][1]);
        *(uint32_t*)&g_P[(size_t)(row + 8) * RNK + nb + 2 * tg] = packh(S[j][2], S[j][3]);
    }
}

// ---------------------------------------------------------------------------
// Column sums, 2-stage deterministic
// ---------------------------------------------------------------------------
__global__ __launch_bounds__(256)
void csum1_kernel(const float* __restrict__ x) {
    __shared__ float red[4][64];
    const int t = threadIdx.x;
    const int d = blockIdx.x * 64 + (t & 63);
    const int b = blockIdx.y;
    const int c = blockIdx.z;
    const int rq = t >> 6;
    const float* xp = x + ((size_t)b * SEQ + (size_t)c * 512 + (size_t)rq * 128) * DIM + d;
    float s = 0.f;
#pragma unroll 8
    for (int r = 0; r < 128; r++) s += xp[(size_t)r * DIM];
    red[rq][t & 63] = s;
    __syncthreads();
    if (rq == 0)
        g_cpart[c][b * DIM + d] = red[0][t] + red[1][t] + red[2][t] + red[3][t];
}
__global__ __launch_bounds__(256)
void csum2_kernel() {
    const int idx = blockIdx.x * 256 + threadIdx.x;
    float s = 0.f;
#pragma unroll
    for (int c = 0; c < 8; c++) s += g_cpart[c][idx];
    g_csum[idx] = s;
}

// ---------------------------------------------------------------------------
// Warp-specialized flash attention.
// grid (64 qtiles, 4 d-slices, 8 batches), 256 thr.
// warps 0-3: PV consumers (16 q rows each); warps 4-7: QK+softmax producers.
// smem: l[64] | PQ 8K | PK 2x8K | PM1 2x8K | V 2x32K
// ---------------------------------------------------------------------------
#define OFF_L   0
#define OFF_PQ  1024
#define OFF_PK  9216
#define OFF_PM  25600
#define OFF_V   41984
#define SMEM_TOTAL 107520

__global__ __launch_bounds__(256, 1)
void attn_kernel(float* __restrict__ out) {
    extern __shared__ char sm[];
    const uint32_t smb = smem_u32(sm);
    const int t = threadIdx.x;
    const int wid = t >> 5, lane = t & 31;
    const int qb = blockIdx.x, z = blockIdx.y, b = blockIdx.z;
    const int tg = lane & 3, g = lane >> 2;
    const int i7 = lane & 7, grp = lane >> 3;
    float* l_s = (float*)(sm + OFF_L);

    const __half* pk_g = g_P + (size_t)b * SEQ * RNK;
    const __half* vh_g = g_xh + (size_t)b * SEQ * DIM + (size_t)z * 256;
    const bool producer = (wid >= 4);

    // ---- prologue (producers): load PQ, prefetch tile 0 ----
    if (producer) {
        const int pt = t - 128;   // 0..127
#pragma unroll
        for (int m = 0; m < 4; m++) {
            int idx = pt + 128 * m;
            int row = idx >> 3, ch = idx & 7;
            uint32_t dst = OFF_PQ + row * 128 + (((uint32_t)(ch ^ (row & 7))) << 4);
            *(uint4*)(sm + dst) =
                *(const uint4*)(g_P + ((size_t)b * SEQ + (size_t)qb * 64 + row) * RNK + ch * 8);
        }
#pragma unroll
        for (int m = 0; m < 4; m++) {
            int idx = pt + 128 * m;
            int row = idx >> 3, ch = idx & 7;
            uint32_t dsw = row * 128 + (((uint32_t)(ch ^ (row & 7))) << 4);
            CP16(smb + OFF_PK + dsw, pk_g + (size_t)row * RNK + ch * 8);
        }
#pragma unroll
        for (int m = 0; m < 16; m++) {
            int idx = pt + 128 * m;
            int row = idx >> 5, ch = idx & 31;
            uint32_t dsw = row * 512 + (((uint32_t)(ch ^ (row & 7))) << 4);
            CP16(smb + OFF_V + dsw, vh_g + (size_t)row * DIM + ch * 8);
        }
        CP_COMMIT();
    }
    __syncthreads();

    if (producer) {
        // ================= producer: QK + softmax =================
        const int pw = wid - 4;
        const int pt = t - 128;
        const uint32_t rowA = pw * 16 + i7 + ((grp & 1) << 3);
        const uint32_t cselA = grp >> 1;
        const uint32_t rowB = i7 + ((grp >> 1) << 3);
        const uint32_t cselB = grp & 1;

        uint32_t aReg[4][4];
#pragma unroll
        for (int kt = 0; kt < 4; kt++)
            ldsm4(aReg[kt], smb + OFF_PQ + rowA * 128 + ((((kt << 1) + cselA) ^ i7) << 4));

        float rl = 0.f, rh = 0.f;
        char* pmBase0 = sm + OFF_PM + pw * 2048;
        const uint32_t off_np_g  = g * 128 + tg * 4;
        const uint32_t off_np_g8 = (g + 8) * 128 + tg * 4;

        for (int it = 0; it < NIT; it++) {
            const int buf = it & 1;
            // guard V/PK buf^1 overwrite: consumers done with PV(it-1)
            if (it >= 1 && it + 1 < NIT) BAR_SYNC(3 + (buf ^ 1));
            if (it + 1 < NIT) {
                const int k0n = (it + 1) * KB;
                const int bo = buf ^ 1;
#pragma unroll
                for (int m = 0; m < 4; m++) {
                    int idx = pt + 128 * m;
                    int row = idx >> 3, ch = idx & 7;
                    uint32_t dsw = row * 128 + (((uint32_t)(ch ^ (row & 7))) << 4);
                    CP16(smb + OFF_PK + bo * 8192 + dsw,
                         pk_g + (size_t)(k0n + row) * RNK + ch * 8);
                }
#pragma unroll
                for (int m = 0; m < 16; m++) {
                    int idx = pt + 128 * m;
                    int row = idx >> 5, ch = idx & 31;
                    uint32_t dsw = row * 512 + (((uint32_t)(ch ^ (row & 7))) << 4);
                    CP16(smb + OFF_V + bo * 32768 + dsw,
                         vh_g + (size_t)(k0n + row) * DIM + ch * 8);
                }
                CP_COMMIT();
                CP_WAIT1();           // tile it resident
            } else {
                CP_WAIT0();
            }

            // QK: 16q x 64k
            float S[8][4];
#pragma unroll
            for (int n = 0; n < 8; n++)
#pragma unroll
                for (int e = 0; e < 4; e++) S[n][e] = 0.f;

            const uint32_t pkBase = smb + OFF_PK + buf * 8192;
#pragma unroll
            for (int kt = 0; kt < 4; kt++) {
#pragma unroll
                for (int np = 0; np < 4; np++) {
                    uint32_t bh[4];
                    ldsm4(bh, pkBase + ((np << 4) + rowB) * 128
                              + ((((kt << 1) + cselB) ^ i7) << 4));
                    mma16816(S[2 * np],     aReg[kt], bh + 0);
                    mma16816(S[2 * np + 1], aReg[kt], bh + 2);
                }
            }

            // softmax probs (logits pre-scaled by log2 e), pm1 pack + STS
            char* pmB = pmBase0 + buf * 8192;
#pragma unroll
            for (int n = 0; n < 8; n++) {
                S[n][0] = ex2(S[n][0]);
                S[n][1] = ex2(S[n][1]);
                S[n][2] = ex2(S[n][2]);
                S[n][3] = ex2(S[n][3]);
                rl += S[n][0] + S[n][1];
                rh += S[n][2] + S[n][3];
                uint32_t sw = ((uint32_t)(n ^ (g & 7))) << 4;
                *(uint32_t*)(pmB + off_np_g  + sw) = packh(S[n][0] - 1.f, S[n][1] - 1.f);
                *(uint32_t*)(pmB + off_np_g8 + sw) = packh(S[n][2] - 1.f, S[n][3] - 1.f);
            }
            BAR_ARRIVE(1 + buf);     // READY[buf]
        }
        // row sums -> smem (single reduction at the end)
        rl += __shfl_xor_sync(0xffffffffu, rl, 1);
        rl += __shfl_xor_sync(0xffffffffu, rl, 2);
        rh += __shfl_xor_sync(0xffffffffu, rh, 1);
        rh += __shfl_xor_sync(0xffffffffu, rh, 2);
        if (tg == 0) {
            l_s[pw * 16 + g] = rl;
            l_s[pw * 16 + g + 8] = rh;
        }
    } else {
        // ================= consumer: PV =================
        const uint32_t rowAp = i7 + ((grp & 1) << 3);
        const uint32_t cselA = grp >> 1;
        const uint32_t rowV = i7 + ((grp & 1) << 3);
        const uint32_t cselV = grp >> 1;

        float Y[32][4];
#pragma unroll
        for (int n = 0; n < 32; n++)
#pragma unroll
            for (int e = 0; e < 4; e++) Y[n][e] = 0.f;

        const uint32_t pmBase0 = smb + OFF_PM + wid * 2048;
        for (int it = 0; it < NIT; it++) {
            const int buf = it & 1;
            BAR_SYNC(1 + buf);        // READY[buf]: pm1 + V visible

            uint32_t Ph[4][4];
            const uint32_t pmB = pmBase0 + buf * 8192;
#pragma unroll
            for (int kt = 0; kt < 4; kt++)
                ldsm4(Ph[kt], pmB + rowAp * 128 + ((((kt << 1) + cselA) ^ i7) << 4));

            const uint32_t vBase = smb + OFF_V + buf * 32768;
#pragma unroll
            for (int kt = 0; kt < 4; kt++) {
                uint32_t vrow = vBase + ((kt << 4) + rowV) * 512;
#pragma unroll
                for (int np = 0; np < 16; np++) {
                    uint32_t bh[4];
                    ldsm4t(bh, vrow + ((((np << 1) + cselV) ^ i7) << 4));
                    mma16816(Y[2 * np],     Ph[kt], bh + 0);
                    mma16816(Y[2 * np + 1], Ph[kt], bh + 2);
                }
            }
            BAR_ARRIVE(3 + buf);      // FREE[buf]
        }

        __syncthreads();              // producers wrote l_s
        const float il = 1.0f / l_s[wid * 16 + g];
        const float ih = 1.0f / l_s[wid * 16 + g + 8];
        const int rlo = qb * 64 + wid * 16 + g;
        const float* cs_base = g_csum + b * DIM + z * 256 + 2 * tg;
        float* o_lo = out + ((size_t)b * SEQ + rlo) * DIM + (size_t)z * 256 + 2 * tg;
        float* o_hi = o_lo + (size_t)8 * DIM;
#pragma unroll
        for (int n = 0; n < 32; n++) {
            float2 cs = *(const float2*)(cs_base + 8 * n);
            float2 p;
            p.x = (Y[n][0] + cs.x) * il; p.y = (Y[n][1] + cs.y) * il;
            *(float2*)(o_lo + 8 * n) = p;
            p.x = (Y[n][2] + cs.x) * ih; p.y = (Y[n][3] + cs.y) * ih;
            *(float2*)(o_hi + 8 * n) = p;
        }
        return;
    }
    __syncthreads();                  // producer side of the epilogue barrier
}

// ---------------------------------------------------------------------------
extern "C" void kernel_launch(void* const* d_in, const int* in_sizes, int n_in,
                              void* d_out, int out_size) {
    const float* x = (const float*)d_in[0];
    const float* Q = (const float*)d_in[1];
    float* out = (float*)d_out;

    cudaFuncSetAttribute(attn_kernel, cudaFuncAttributeMaxDynamicSharedMemorySize,
                         SMEM_TOTAL);
    cudaFuncSetAttribute(projH_kernel, cudaFuncAttributeMaxDynamicSharedMemorySize,
                         PSM_TOTAL);

    cvt_kernel<<<(size_t)BATCH * SEQ * DIM / 4 / 256, 256>>>(x);
    qprep_kernel<<<DIM / 64, 256>>>(Q);
    projH_kernel<<<BATCH * SEQ / 128, 256, PSM_TOTAL>>>();
    csum1_kernel<<<dim3(DIM / 64, BATCH, 8), 256>>>(x);
    csum2_kernel<<<BATCH * DIM / 256, 256>>>();
    attn_kernel<<<dim3(SEQ / 64, DIM / 256, BATCH), 256, SMEM_TOTAL>>>(out);
}

// round 8
// speedup vs baseline: 1.2791x; 1.2791x over previous
#include <cuda_runtime.h>
#include <cuda_fp16.h>
#include <cstdint>

#define BATCH 8
#define SEQ   4096
#define DIM   1024
#define RNK   64
#define KB    64
#define NIT   (SEQ/KB)

// ---------------- global scratch ----------------
__device__ __align__(16) __half g_P[BATCH * SEQ * RNK];
__device__ __align__(16) __half g_xh[(size_t)BATCH * SEQ * DIM];
__device__ __align__(16) __half g_Qt[RNK * DIM];          // Q^T * sqrt(log2e)/32, fp16
__device__ __align__(16) float  g_csum[BATCH * DIM];
__device__ __align__(16) float  g_cpart[8][BATCH * DIM];

// ---------------- helpers ----------------
__device__ __forceinline__ uint32_t smem_u32(const void* p) {
    uint32_t a;
    asm("{ .reg .u64 t; cvta.to.shared.u64 t, %1; cvt.u32.u64 %0, t; }" : "=r"(a) : "l"(p));
    return a;
}
__device__ __forceinline__ void ldsm4(uint32_t* r, uint32_t a) {
    asm volatile("ldmatrix.sync.aligned.m8n8.x4.shared.b16 {%0,%1,%2,%3}, [%4];"
        : "=r"(r[0]), "=r"(r[1]), "=r"(r[2]), "=r"(r[3]) : "r"(a));
}
__device__ __forceinline__ void ldsm4t(uint32_t* r, uint32_t a) {
    asm volatile("ldmatrix.sync.aligned.m8n8.x4.trans.shared.b16 {%0,%1,%2,%3}, [%4];"
        : "=r"(r[0]), "=r"(r[1]), "=r"(r[2]), "=r"(r[3]) : "r"(a));
}
__device__ __forceinline__ void mma16816(float* d, const uint32_t* a, const uint32_t* b) {
    asm volatile(
        "mma.sync.aligned.m16n8k16.row.col.f32.f16.f16.f32 "
        "{%0,%1,%2,%3}, {%4,%5,%6,%7}, {%8,%9}, {%0,%1,%2,%3};"
        : "+f"(d[0]), "+f"(d[1]), "+f"(d[2]), "+f"(d[3])
        : "r"(a[0]), "r"(a[1]), "r"(a[2]), "r"(a[3]), "r"(b[0]), "r"(b[1]));
}
#define CP16(dst, src) \
    asm volatile("cp.async.cg.shared.global [%0], [%1], 16;" :: "r"(dst), "l"(src))
#define CP_COMMIT() asm volatile("cp.async.commit_group;" ::: "memory")
#define CP_WAIT0()  asm volatile("cp.async.wait_group 0;" ::: "memory")

__device__ __forceinline__ uint32_t packh(float a, float b) {
    __half2 h = __floats2half2_rn(a, b);
    return *(uint32_t*)&h;
}
// exp with log2e pre-folded into the logits: p = 2^s (single MUFU op)
__device__ __forceinline__ float ex2(float s) {
    float p;
    asm("ex2.approx.f32 %0, %1;" : "=f"(p) : "f"(s));
    return p;
}

// ---------------------------------------------------------------------------
// cvt: x fp32 -> fp16 (streaming)
// ---------------------------------------------------------------------------
__global__ __launch_bounds__(256)
void cvt_kernel(const float* __restrict__ x) {
    size_t idx = (size_t)blockIdx.x * 256 + threadIdx.x;
    float4 v = ((const float4*)x)[idx];
    ((uint2*)g_xh)[idx] = make_uint2(packh(v.x, v.y), packh(v.z, v.w));
}

// ---------------------------------------------------------------------------
// qprep: Q -> g_Qt [64 n][1024 k] fp16, scaled by sqrt(log2 e)/32
// ---------------------------------------------------------------------------
__global__ __launch_bounds__(256)
void qprep_kernel(const float* __restrict__ Q) {
    __shared__ float ts[64][65];
    const int t = threadIdx.x;
    const int k0 = blockIdx.x * 64;
    const int r = t >> 2, cb = (t & 3) << 4;
    const float SC = 0.037535075274576556f;   // sqrt(log2 e) / 32
    const float* qp = Q + (size_t)(k0 + r) * RNK + cb;
#pragma unroll
    for (int m = 0; m < 4; m++) {
        float4 v = *(const float4*)(qp + 4 * m);
        ts[r][cb + 4 * m + 0] = v.x * SC;
        ts[r][cb + 4 * m + 1] = v.y * SC;
        ts[r][cb + 4 * m + 2] = v.z * SC;
        ts[r][cb + 4 * m + 3] = v.w * SC;
    }
    __syncthreads();
    __half* o = g_Qt + (size_t)r * DIM + k0 + cb;
#pragma unroll
    for (int m = 0; m < 2; m++) {
        uint32_t w[4];
#pragma unroll
        for (int p = 0; p < 4; p++)
            w[p] = packh(ts[cb + 8 * m + 2 * p][r], ts[cb + 8 * m + 2 * p + 1][r]);
        *(uint4*)(o + 8 * m) = make_uint4(w[0], w[1], w[2], w[3]);
    }
}

// ---------------------------------------------------------------------------
// projH: P = x_h @ Qt^T via HMMA
// ---------------------------------------------------------------------------
#define POFF_X 0
#define POFF_Q 32768
#define PSM_TOTAL 49152

__global__ __launch_bounds__(256, 2)
void projH_kernel() {
    extern __shared__ char sm[];
    const uint32_t smb = smem_u32(sm);
    const int t = threadIdx.x;
    const int warp = t >> 5, lane = t & 31;
    const int row0 = blockIdx.x * 128;
    const int q0 = warp * 16;
    const int tg = lane & 3, g = lane >> 2;
    const int i7 = lane & 7, grp = lane >> 3;

    {
#pragma unroll
        for (int m = 0; m < 4; m++) {
            int idx = t + 256 * m;
            int row = idx >> 3, ch = idx & 7;
            uint32_t dsw = row * 128 + (((uint32_t)(ch ^ (row & 7))) << 4);
            CP16(smb + POFF_X + dsw, g_xh + (size_t)(row0 + row) * DIM + ch * 8);
        }
#pragma unroll
        for (int m = 0; m < 2; m++) {
            int idx = t + 256 * m;
            int row = idx >> 3, ch = idx & 7;
            uint32_t dsw = row * 128 + (((uint32_t)(ch ^ (row & 7))) << 4);
            CP16(smb + POFF_Q + dsw, g_Qt + (size_t)row * DIM + ch * 8);
        }
        CP_COMMIT();
    }

    const uint32_t rowA = q0 + i7 + ((grp & 1) << 3);
    const uint32_t cselA = grp >> 1;
    const uint32_t rowB = i7 + ((grp >> 1) << 3);
    const uint32_t cselB = grp & 1;

    float S[8][4];
#pragma unroll
    for (int n = 0; n < 8; n++)
#pragma unroll
        for (int e = 0; e < 4; e++) S[n][e] = 0.f;

    for (int c = 0; c < 16; c++) {
        const int buf = c & 1;
        CP_WAIT0();
        __syncthreads();
        if (c + 1 < 16) {
            const int kc = (c + 1) * 64;
            const int bo = buf ^ 1;
#pragma unroll
            for (int m = 0; m < 4; m++) {
                int idx = t + 256 * m;
                int row = idx >> 3, ch = idx & 7;
                uint32_t dsw = row * 128 + (((uint32_t)(ch ^ (row & 7))) << 4);
                CP16(smb + POFF_X + bo * 16384 + dsw,
                     g_xh + (size_t)(row0 + row) * DIM + kc + ch * 8);
            }
#pragma unroll
            for (int m = 0; m < 2; m++) {
                int idx = t + 256 * m;
                int row = idx >> 3, ch = idx & 7;
                uint32_t dsw = row * 128 + (((uint32_t)(ch ^ (row & 7))) << 4);
                CP16(smb + POFF_Q + bo * 8192 + dsw,
                     g_Qt + (size_t)row * DIM + kc + ch * 8);
            }
            CP_COMMIT();
        }
        const uint32_t xb = smb + POFF_X + buf * 16384;
        const uint32_t qb = smb + POFF_Q + buf * 8192;
#pragma unroll
        for (int kt = 0; kt < 4; kt++) {
            uint32_t ah[4];
            ldsm4(ah, xb + rowA * 128 + ((((kt << 1) + cselA) ^ i7) << 4));
#pragma unroll
            for (int np = 0; np < 4; np++) {
                uint32_t bh[4];
                ldsm4(bh, qb + ((np << 4) + rowB) * 128
                          + ((((kt << 1) + cselB) ^ i7) << 4));
                mma16816(S[2 * np],     ah, bh + 0);
                mma16816(S[2 * np + 1], ah, bh + 2);
            }
        }
        __syncthreads();
    }

    const int row = row0 + q0 + g;
#pragma unroll
    for (int j = 0; j < 8; j++) {
        const int nb = (j >> 1) * 16 + (j & 1) * 8;
        *(uint32_t*)&g_P[(size_t)row * RNK + nb + 2 * tg] = packh(S[j][0], S[j][1]);
        *(uint32_t*)&g_P[(size_t)(row + 8) * RNK + nb + 2 * tg] = packh(S[j][2], S[j][3]);
    }
}

// ---------------------------------------------------------------------------
// Column sums, 2-stage deterministic
// ---------------------------------------------------------------------------
__global__ __launch_bounds__(256)
void csum1_kernel(const float* __restrict__ x) {
    __shared__ float red[4][64];
    const int t = threadIdx.x;
    const int d = blockIdx.x * 64 + (t & 63);
    const int b = blockIdx.y;
    const int c = blockIdx.z;
    const int rq = t >> 6;
    const float* xp = x + ((size_t)b * SEQ + (size_t)c * 512 + (size_t)rq * 128) * DIM + d;
    float s = 0.f;
#pragma unroll 8
    for (int r = 0; r < 128; r++) s += xp[(size_t)r * DIM];
    red[rq][t & 63] = s;
    __syncthreads();
    if (rq == 0)
        g_cpart[c][b * DIM + d] = red[0][t] + red[1][t] + red[2][t] + red[3][t];
}
__global__ __launch_bounds__(256)
void csum2_kernel() {
    const int idx = blockIdx.x * 256 + threadIdx.x;
    float s = 0.f;
#pragma unroll
    for (int c = 0; c < 8; c++) s += g_cpart[c][idx];
    g_csum[idx] = s;
}

// ---------------------------------------------------------------------------
// Flash attention, fp16 HMMA, softmax interleaved into PV per-kt.
// grid (32 qtiles, 4 d-slices, 8 batches), 256 threads.
// smem: PQ 16K | PK 2x8K | V 2x32K = 96K
// ---------------------------------------------------------------------------
#define OFF_PQ   0
#define OFF_PK   16384
#define OFF_V    32768
#define SMEM_TOTAL 98304

__global__ __launch_bounds__(256, 1)
void attn_kernel(float* __restrict__ out) {
    extern __shared__ char sm[];
    const uint32_t smb = smem_u32(sm);
    const int t = threadIdx.x;
    const int warp = t >> 5, lane = t & 31;
    const int qb = blockIdx.x, z = blockIdx.y, b = blockIdx.z;
    const int q0 = warp * 16;
    const int tg = lane & 3, g = lane >> 2;
    const int i7 = lane & 7, grp = lane >> 3;

    const __half* pk_g = g_P + (size_t)b * SEQ * RNK;
    const __half* vh_g = g_xh + (size_t)b * SEQ * DIM + (size_t)z * 256;

    // ---- load Pq tile [128 q][64 r] into smem (swizzled) ----
#pragma unroll
    for (int m = 0; m < 4; m++) {
        int idx = t + 256 * m;
        int row = idx >> 3, ch = idx & 7;
        size_t src = ((size_t)b * SEQ + (size_t)qb * 128 + row) * RNK + ch * 8;
        uint32_t dst = row * 128 + (((uint32_t)(ch ^ (row & 7))) << 4);
        *(uint4*)(sm + OFF_PQ + dst) = *(const uint4*)(g_P + src);
    }
    // ---- prefetch tile 0 ----
    {
#pragma unroll
        for (int m = 0; m < 2; m++) {
            int idx = t + 256 * m;
            int row = idx >> 3, ch = idx & 7;
            uint32_t dsw = row * 128 + (((uint32_t)(ch ^ (row & 7))) << 4);
            CP16(smb + OFF_PK + dsw, pk_g + (size_t)row * RNK + ch * 8);
        }
#pragma unroll
        for (int m = 0; m < 8; m++) {
            int idx = t + 256 * m;
            int row = idx >> 5, ch = idx & 31;
            uint32_t dsw = row * 512 + (((uint32_t)(ch ^ (row & 7))) << 4);
            CP16(smb + OFF_V + dsw, vh_g + (size_t)row * DIM + ch * 8);
        }
        CP_COMMIT();
    }
    __syncthreads();

    // ---- hoist Pq A-fragments into registers ----
    const uint32_t rowA = q0 + i7 + ((grp & 1) << 3);
    const uint32_t cselA = grp >> 1;
    uint32_t aReg[4][4];
#pragma unroll
    for (int kt = 0; kt < 4; kt++)
        ldsm4(aReg[kt], smb + OFF_PQ + rowA * 128 + ((((kt << 1) + cselA) ^ i7) << 4));

    float Y[32][4];
#pragma unroll
    for (int n = 0; n < 32; n++)
#pragma unroll
        for (int e = 0; e < 4; e++) Y[n][e] = 0.f;
    float rl = 0.f, rh = 0.f;   // per-lane row-sum accumulators (reduced once at end)

    const uint32_t rowB = i7 + ((grp >> 1) << 3);
    const uint32_t cselB = grp & 1;
    const uint32_t rowV = i7 + ((grp & 1) << 3);
    const uint32_t cselV = grp >> 1;

    for (int it = 0; it < NIT; it++) {
        const int buf = it & 1;
        CP_WAIT0();
        __syncthreads();

        // prefetch tile it+1 (overlaps compute)
        if (it + 1 < NIT) {
            const int k0n = (it + 1) * KB;
            const int bo = buf ^ 1;
#pragma unroll
            for (int m = 0; m < 2; m++) {
                int idx = t + 256 * m;
                int row = idx >> 3, ch = idx & 7;
                uint32_t dsw = row * 128 + (((uint32_t)(ch ^ (row & 7))) << 4);
                CP16(smb + OFF_PK + bo * 8192 + dsw,
                     pk_g + (size_t)(k0n + row) * RNK + ch * 8);
            }
#pragma unroll
            for (int m = 0; m < 8; m++) {
                int idx = t + 256 * m;
                int row = idx >> 5, ch = idx & 31;
                uint32_t dsw = row * 512 + (((uint32_t)(ch ^ (row & 7))) << 4);
                CP16(smb + OFF_V + bo * 32768 + dsw,
                     vh_g + (size_t)(k0n + row) * DIM + ch * 8);
            }
            CP_COMMIT();
        }

        // ---- QK^T (single combo; logits pre-scaled by log2 e) ----
        float S[8][4];
#pragma unroll
        for (int n = 0; n < 8; n++)
#pragma unroll
            for (int e = 0; e < 4; e++) S[n][e] = 0.f;

        const uint32_t pkBase = smb + OFF_PK + buf * 8192;
#pragma unroll
        for (int kt = 0; kt < 4; kt++) {
#pragma unroll
            for (int np = 0; np < 4; np++) {
                uint32_t bh[4];
                ldsm4(bh, pkBase + ((np << 4) + rowB) * 128
                          + ((((kt << 1) + cselB) ^ i7) << 4));
                mma16816(S[2 * np],     aReg[kt], bh + 0);
                mma16816(S[2 * np + 1], aReg[kt], bh + 2);
            }
        }

        // ---- interleaved: per-kt softmax (MUFU) then PV mma (tensor) ----
        const uint32_t vBase = smb + OFF_V + buf * 32768;
#pragma unroll
        for (int kt = 0; kt < 4; kt++) {
            const int n0 = 2 * kt;
            S[n0][0] = ex2(S[n0][0]);   S[n0][1] = ex2(S[n0][1]);
            S[n0][2] = ex2(S[n0][2]);   S[n0][3] = ex2(S[n0][3]);
            S[n0+1][0] = ex2(S[n0+1][0]); S[n0+1][1] = ex2(S[n0+1][1]);
            S[n0+1][2] = ex2(S[n0+1][2]); S[n0+1][3] = ex2(S[n0+1][3]);
            rl += S[n0][0] + S[n0][1] + S[n0+1][0] + S[n0+1][1];
            rh += S[n0][2] + S[n0][3] + S[n0+1][2] + S[n0+1][3];
            uint32_t Ph[4];
            Ph[0] = packh(S[n0][0] - 1.f,   S[n0][1] - 1.f);
            Ph[1] = packh(S[n0][2] - 1.f,   S[n0][3] - 1.f);
            Ph[2] = packh(S[n0+1][0] - 1.f, S[n0+1][1] - 1.f);
            Ph[3] = packh(S[n0+1][2] - 1.f, S[n0+1][3] - 1.f);

            uint32_t vrow = vBase + ((kt << 4) + rowV) * 512;
#pragma unroll
            for (int np = 0; np < 16; np++) {
                uint32_t bh[4];
                ldsm4t(bh, vrow + ((((np << 1) + cselV) ^ i7) << 4));
                mma16816(Y[2 * np],     Ph, bh + 0);
                mma16816(Y[2 * np + 1], Ph, bh + 2);
            }
        }
    }

    // ---- single row-sum reduction at the end ----
    rl += __shfl_xor_sync(0xffffffffu, rl, 1);
    rl += __shfl_xor_sync(0xffffffffu, rl, 2);
    rh += __shfl_xor_sync(0xffffffffu, rh, 1);
    rh += __shfl_xor_sync(0xffffffffu, rh, 2);

    // ---- epilogue: y = (csum + Ydot) / l ----
    const float il = 1.0f / rl;
    const float ih = 1.0f / rh;
    const int rlo = qb * 128 + q0 + g;
    const float* cs_base = g_csum + b * DIM + z * 256 + 2 * tg;
    float* o_lo = out + ((size_t)b * SEQ + rlo) * DIM + (size_t)z * 256 + 2 * tg;
    float* o_hi = o_lo + (size_t)8 * DIM;
#pragma unroll
    for (int n = 0; n < 32; n++) {
        float2 cs = *(const float2*)(cs_base + 8 * n);
        float2 p;
        p.x = (Y[n][0] + cs.x) * il; p.y = (Y[n][1] + cs.y) * il;
        *(float2*)(o_lo + 8 * n) = p;
        p.x = (Y[n][2] + cs.x) * ih; p.y = (Y[n][3] + cs.y) * ih;
        *(float2*)(o_hi + 8 * n) = p;
    }
}

// ---------------------------------------------------------------------------
extern "C" void kernel_launch(void* const* d_in, const int* in_sizes, int n_in,
                              void* d_out, int out_size) {
    const float* x = (const float*)d_in[0];
    const float* Q = (const float*)d_in[1];
    float* out = (float*)d_out;

    cudaFuncSetAttribute(attn_kernel, cudaFuncAttributeMaxDynamicSharedMemorySize,
                         SMEM_TOTAL);
    cudaFuncSetAttribute(projH_kernel, cudaFuncAttributeMaxDynamicSharedMemorySize,
                         PSM_TOTAL);

    cvt_kernel<<<(size_t)BATCH * SEQ * DIM / 4 / 256, 256>>>(x);
    qprep_kernel<<<DIM / 64, 256>>>(Q);
    projH_kernel<<<BATCH * SEQ / 128, 256, PSM_TOTAL>>>();
    csum1_kernel<<<dim3(DIM / 64, BATCH, 8), 256>>>(x);
    csum2_kernel<<<BATCH * DIM / 256, 256>>>();
    attn_kernel<<<dim3(SEQ / 128, DIM / 256, BATCH), 256, SMEM_TOTAL>>>(out);
}

// round 9
// speedup vs baseline: 1.2818x; 1.0022x over previous
#include <cuda_runtime.h>
#include <cuda_fp16.h>
#include <cstdint>

#define BATCH 8
#define SEQ   4096
#define DIM   1024
#define RNK   64
#define KB    128
#define NIT   (SEQ/KB)

// ---------------- global scratch ----------------
__device__ __align__(16) __half g_P[BATCH * SEQ * RNK];
__device__ __align__(16) __half g_xh[(size_t)BATCH * SEQ * DIM];
__device__ __align__(16) __half g_Qt[RNK * DIM];          // Q^T * sqrt(log2e)/32, fp16
__device__ __align__(16) float  g_csum[BATCH * DIM];
__device__ __align__(16) float  g_cpart[32][BATCH * DIM];

// ---------------- helpers ----------------
__device__ __forceinline__ uint32_t smem_u32(const void* p) {
    uint32_t a;
    asm("{ .reg .u64 t; cvta.to.shared.u64 t, %1; cvt.u32.u64 %0, t; }" : "=r"(a) : "l"(p));
    return a;
}
__device__ __forceinline__ void ldsm4(uint32_t* r, uint32_t a) {
    asm volatile("ldmatrix.sync.aligned.m8n8.x4.shared.b16 {%0,%1,%2,%3}, [%4];"
        : "=r"(r[0]), "=r"(r[1]), "=r"(r[2]), "=r"(r[3]) : "r"(a));
}
__device__ __forceinline__ void ldsm4t(uint32_t* r, uint32_t a) {
    asm volatile("ldmatrix.sync.aligned.m8n8.x4.trans.shared.b16 {%0,%1,%2,%3}, [%4];"
        : "=r"(r[0]), "=r"(r[1]), "=r"(r[2]), "=r"(r[3]) : "r"(a));
}
__device__ __forceinline__ void mma16816(float* d, const uint32_t* a, const uint32_t* b) {
    asm volatile(
        "mma.sync.aligned.m16n8k16.row.col.f32.f16.f16.f32 "
        "{%0,%1,%2,%3}, {%4,%5,%6,%7}, {%8,%9}, {%0,%1,%2,%3};"
        : "+f"(d[0]), "+f"(d[1]), "+f"(d[2]), "+f"(d[3])
        : "r"(a[0]), "r"(a[1]), "r"(a[2]), "r"(a[3]), "r"(b[0]), "r"(b[1]));
}
#define CP16(dst, src) \
    asm volatile("cp.async.cg.shared.global [%0], [%1], 16;" :: "r"(dst), "l"(src))
#define CP_COMMIT() asm volatile("cp.async.commit_group;" ::: "memory")
#define CP_WAIT0()  asm volatile("cp.async.wait_group 0;" ::: "memory")

__device__ __forceinline__ uint32_t packh(float a, float b) {
    __half2 h = __floats2half2_rn(a, b);
    return *(uint32_t*)&h;
}
// exp with log2e pre-folded into the logits: p = 2^s (single MUFU op)
__device__ __forceinline__ float ex2(float s) {
    float p;
    asm("ex2.approx.f32 %0, %1;" : "=f"(p) : "f"(s));
    return p;
}

// ---------------------------------------------------------------------------
// Fused cvt + csum: x fp32 -> fp16, and per-128-row-chunk column sums.
// grid (SEQ/128, BATCH). Thread t owns columns 4t..4t+3 for its chunk.
// ---------------------------------------------------------------------------
__global__ __launch_bounds__(256)
void cvtsum_kernel(const float* __restrict__ x) {
    const int t = threadIdx.x;
    const int sc = blockIdx.x, b = blockIdx.y;
    const float* xp = x + ((size_t)b * SEQ + (size_t)sc * 128) * DIM + 4 * t;
    __half* op = g_xh + ((size_t)b * SEQ + (size_t)sc * 128) * DIM + 4 * t;
    float s0 = 0.f, s1 = 0.f, s2 = 0.f, s3 = 0.f;
#pragma unroll 4
    for (int r = 0; r < 128; r++) {
        float4 v = *(const float4*)(xp + (size_t)r * DIM);
        s0 += v.x; s1 += v.y; s2 += v.z; s3 += v.w;
        *(uint2*)(op + (size_t)r * DIM) = make_uint2(packh(v.x, v.y), packh(v.z, v.w));
    }
    float* cp = g_cpart[sc] + b * DIM + 4 * t;
    cp[0] = s0; cp[1] = s1; cp[2] = s2; cp[3] = s3;
}
__global__ __launch_bounds__(256)
void csum2_kernel() {
    const int idx = blockIdx.x * 256 + threadIdx.x;
    float s = 0.f;
#pragma unroll
    for (int c = 0; c < 32; c++) s += g_cpart[c][idx];
    g_csum[idx] = s;
}

// ---------------------------------------------------------------------------
// qprep: Q -> g_Qt [64 n][1024 k] fp16, scaled by sqrt(log2 e)/32
// ---------------------------------------------------------------------------
__global__ __launch_bounds__(256)
void qprep_kernel(const float* __restrict__ Q) {
    __shared__ float ts[64][65];
    const int t = threadIdx.x;
    const int k0 = blockIdx.x * 64;
    const int r = t >> 2, cb = (t & 3) << 4;
    const float SC = 0.037535075274576556f;   // sqrt(log2 e) / 32
    const float* qp = Q + (size_t)(k0 + r) * RNK + cb;
#pragma unroll
    for (int m = 0; m < 4; m++) {
        float4 v = *(const float4*)(qp + 4 * m);
        ts[r][cb + 4 * m + 0] = v.x * SC;
        ts[r][cb + 4 * m + 1] = v.y * SC;
        ts[r][cb + 4 * m + 2] = v.z * SC;
        ts[r][cb + 4 * m + 3] = v.w * SC;
    }
    __syncthreads();
    __half* o = g_Qt + (size_t)r * DIM + k0 + cb;
#pragma unroll
    for (int m = 0; m < 2; m++) {
        uint32_t w[4];
#pragma unroll
        for (int p = 0; p < 4; p++)
            w[p] = packh(ts[cb + 8 * m + 2 * p][r], ts[cb + 8 * m + 2 * p + 1][r]);
        *(uint4*)(o + 8 * m) = make_uint4(w[0], w[1], w[2], w[3]);
    }
}

// ---------------------------------------------------------------------------
// projH: P = x_h @ Qt^T via HMMA
// ---------------------------------------------------------------------------
#define POFF_X 0
#define POFF_Q 32768
#define PSM_TOTAL 49152

__global__ __launch_bounds__(256, 2)
void projH_kernel() {
    extern __shared__ char sm[];
    const uint32_t smb = smem_u32(sm);
    const int t = threadIdx.x;
    const int warp = t >> 5, lane = t & 31;
    const int row0 = blockIdx.x * 128;
    const int q0 = warp * 16;
    const int tg = lane & 3, g = lane >> 2;
    const int i7 = lane & 7, grp = lane >> 3;

    {
#pragma unroll
        for (int m = 0; m < 4; m++) {
            int idx = t + 256 * m;
            int row = idx >> 3, ch = idx & 7;
            uint32_t dsw = row * 128 + (((uint32_t)(ch ^ (row & 7))) << 4);
            CP16(smb + POFF_X + dsw, g_xh + (size_t)(row0 + row) * DIM + ch * 8);
        }
#pragma unroll
        for (int m = 0; m < 2; m++) {
            int idx = t + 256 * m;
            int row = idx >> 3, ch = idx & 7;
            uint32_t dsw = row * 128 + (((uint32_t)(ch ^ (row & 7))) << 4);
            CP16(smb + POFF_Q + dsw, g_Qt + (size_t)row * DIM + ch * 8);
        }
        CP_COMMIT();
    }

    const uint32_t rowA = q0 + i7 + ((grp & 1) << 3);
    const uint32_t cselA = grp >> 1;
    const uint32_t rowB = i7 + ((grp >> 1) << 3);
    const uint32_t cselB = grp & 1;

    float S[8][4];
#pragma unroll
    for (int n = 0; n < 8; n++)
#pragma unroll
        for (int e = 0; e < 4; e++) S[n][e] = 0.f;

    for (int c = 0; c < 16; c++) {
        const int buf = c & 1;
        CP_WAIT0();
        __syncthreads();
        if (c + 1 < 16) {
            const int kc = (c + 1) * 64;
            const int bo = buf ^ 1;
#pragma unroll
            for (int m = 0; m < 4; m++) {
                int idx = t + 256 * m;
                int row = idx >> 3, ch = idx & 7;
                uint32_t dsw = row * 128 + (((uint32_t)(ch ^ (row & 7))) << 4);
                CP16(smb + POFF_X + bo * 16384 + dsw,
                     g_xh + (size_t)(row0 + row) * DIM + kc + ch * 8);
            }
#pragma unroll
            for (int m = 0; m < 2; m++) {
                int idx = t + 256 * m;
                int row = idx >> 3, ch = idx & 7;
                uint32_t dsw = row * 128 + (((uint32_t)(ch ^ (row & 7))) << 4);
                CP16(smb + POFF_Q + bo * 8192 + dsw,
                     g_Qt + (size_t)row * DIM + kc + ch * 8);
            }
            CP_COMMIT();
        }
        const uint32_t xb = smb + POFF_X + buf * 16384;
        const uint32_t qb = smb + POFF_Q + buf * 8192;
#pragma unroll
        for (int kt = 0; kt < 4; kt++) {
            uint32_t ah[4];
            ldsm4(ah, xb + rowA * 128 + ((((kt << 1) + cselA) ^ i7) << 4));
#pragma unroll
            for (int np = 0; np < 4; np++) {
                uint32_t bh[4];
                ldsm4(bh, qb + ((np << 4) + rowB) * 128
                          + ((((kt << 1) + cselB) ^ i7) << 4));
                mma16816(S[2 * np],     ah, bh + 0);
                mma16816(S[2 * np + 1], ah, bh + 2);
            }
        }
        __syncthreads();
    }

    const int row = row0 + q0 + g;
#pragma unroll
    for (int j = 0; j < 8; j++) {
        const int nb = (j >> 1) * 16 + (j & 1) * 8;
        *(uint32_t*)&g_P[(size_t)row * RNK + nb + 2 * tg] = packh(S[j][0], S[j][1]);
        *(uint32_t*)&g_P[(size_t)(row + 8) * RNK + nb + 2 * tg] = packh(S[j][2], S[j][3]);
    }
}

// ---------------------------------------------------------------------------
// Flash attention, fp16 HMMA, KB=128 buffers with two 64-key subtiles.
// grid (32 qtiles, 4 d-slices, 8 batches), 256 threads.
// smem: PQ 16K | PK 2x16K | V 2x64K = 176K
// ---------------------------------------------------------------------------
#define OFF_PQ   0
#define OFF_PK   16384
#define OFF_V    49152
#define SMEM_TOTAL 180224

__global__ __launch_bounds__(256, 1)
void attn_kernel(float* __restrict__ out) {
    extern __shared__ char sm[];
    const uint32_t smb = smem_u32(sm);
    const int t = threadIdx.x;
    const int warp = t >> 5, lane = t & 31;
    const int qb = blockIdx.x, z = blockIdx.y, b = blockIdx.z;
    const int q0 = warp * 16;
    const int tg = lane & 3, g = lane >> 2;
    const int i7 = lane & 7, grp = lane >> 3;

    const __half* pk_g = g_P + (size_t)b * SEQ * RNK;
    const __half* vh_g = g_xh + (size_t)b * SEQ * DIM + (size_t)z * 256;

    // ---- load Pq tile [128 q][64 r] into smem (swizzled) ----
#pragma unroll
    for (int m = 0; m < 4; m++) {
        int idx = t + 256 * m;
        int row = idx >> 3, ch = idx & 7;
        size_t src = ((size_t)b * SEQ + (size_t)qb * 128 + row) * RNK + ch * 8;
        uint32_t dst = row * 128 + (((uint32_t)(ch ^ (row & 7))) << 4);
        *(uint4*)(sm + OFF_PQ + dst) = *(const uint4*)(g_P + src);
    }
    // ---- prefetch tile 0 (128 keys) ----
    {
#pragma unroll
        for (int m = 0; m < 4; m++) {
            int idx = t + 256 * m;
            int row = idx >> 3, ch = idx & 7;
            uint32_t dsw = row * 128 + (((uint32_t)(ch ^ (row & 7))) << 4);
            CP16(smb + OFF_PK + dsw, pk_g + (size_t)row * RNK + ch * 8);
        }
#pragma unroll
        for (int m = 0; m < 16; m++) {
            int idx = t + 256 * m;
            int row = idx >> 5, ch = idx & 31;
            uint32_t dsw = row * 512 + (((uint32_t)(ch ^ (row & 7))) << 4);
            CP16(smb + OFF_V + dsw, vh_g + (size_t)row * DIM + ch * 8);
        }
        CP_COMMIT();
    }
    __syncthreads();

    // ---- hoist Pq A-fragments into registers ----
    const uint32_t rowA = q0 + i7 + ((grp & 1) << 3);
    const uint32_t cselA = grp >> 1;
    uint32_t aReg[4][4];
#pragma unroll
    for (int kt = 0; kt < 4; kt++)
        ldsm4(aReg[kt], smb + OFF_PQ + rowA * 128 + ((((kt << 1) + cselA) ^ i7) << 4));

    float Y[32][4];
#pragma unroll
    for (int n = 0; n < 32; n++)
#pragma unroll
        for (int e = 0; e < 4; e++) Y[n][e] = 0.f;
    float rl = 0.f, rh = 0.f;

    const uint32_t rowB = i7 + ((grp >> 1) << 3);
    const uint32_t cselB = grp & 1;
    const uint32_t rowV = i7 + ((grp & 1) << 3);
    const uint32_t cselV = grp >> 1;

    for (int it = 0; it < NIT; it++) {
        const int buf = it & 1;
        CP_WAIT0();
        __syncthreads();

        // prefetch tile it+1 (overlaps compute)
        if (it + 1 < NIT) {
            const int k0n = (it + 1) * KB;
            const int bo = buf ^ 1;
#pragma unroll
            for (int m = 0; m < 4; m++) {
                int idx = t + 256 * m;
                int row = idx >> 3, ch = idx & 7;
                uint32_t dsw = row * 128 + (((uint32_t)(ch ^ (row & 7))) << 4);
                CP16(smb + OFF_PK + bo * 16384 + dsw,
                     pk_g + (size_t)(k0n + row) * RNK + ch * 8);
            }
#pragma unroll
            for (int m = 0; m < 16; m++) {
                int idx = t + 256 * m;
                int row = idx >> 5, ch = idx & 31;
                uint32_t dsw = row * 512 + (((uint32_t)(ch ^ (row & 7))) << 4);
                CP16(smb + OFF_V + bo * 65536 + dsw,
                     vh_g + (size_t)(k0n + row) * DIM + ch * 8);
            }
            CP_COMMIT();
        }

        // ---- two 64-key subtiles within the buffer ----
#pragma unroll
        for (int sub = 0; sub < 2; sub++) {
            const uint32_t pkBase = smb + OFF_PK + buf * 16384 + sub * 8192;
            const uint32_t vBase  = smb + OFF_V  + buf * 65536 + sub * 32768;

            // QK^T (single combo; logits pre-scaled by log2 e)
            float S[8][4];
#pragma unroll
            for (int n = 0; n < 8; n++)
#pragma unroll
                for (int e = 0; e < 4; e++) S[n][e] = 0.f;

#pragma unroll
            for (int kt = 0; kt < 4; kt++) {
#pragma unroll
                for (int np = 0; np < 4; np++) {
                    uint32_t bh[4];
                    ldsm4(bh, pkBase + ((np << 4) + rowB) * 128
                              + ((((kt << 1) + cselB) ^ i7) << 4));
                    mma16816(S[2 * np],     aReg[kt], bh + 0);
                    mma16816(S[2 * np + 1], aReg[kt], bh + 2);
                }
            }

            // interleaved per-kt softmax (MUFU) + PV mma (tensor)
#pragma unroll
            for (int kt = 0; kt < 4; kt++) {
                const int n0 = 2 * kt;
                S[n0][0] = ex2(S[n0][0]);     S[n0][1] = ex2(S[n0][1]);
                S[n0][2] = ex2(S[n0][2]);     S[n0][3] = ex2(S[n0][3]);
                S[n0+1][0] = ex2(S[n0+1][0]); S[n0+1][1] = ex2(S[n0+1][1]);
                S[n0+1][2] = ex2(S[n0+1][2]); S[n0+1][3] = ex2(S[n0+1][3]);
                rl += S[n0][0] + S[n0][1] + S[n0+1][0] + S[n0+1][1];
                rh += S[n0][2] + S[n0][3] + S[n0+1][2] + S[n0+1][3];
                uint32_t Ph[4];
                Ph[0] = packh(S[n0][0] - 1.f,   S[n0][1] - 1.f);
                Ph[1] = packh(S[n0][2] - 1.f,   S[n0][3] - 1.f);
                Ph[2] = packh(S[n0+1][0] - 1.f, S[n0+1][1] - 1.f);
                Ph[3] = packh(S[n0+1][2] - 1.f, S[n0+1][3] - 1.f);

                uint32_t vrow = vBase + ((kt << 4) + rowV) * 512;
#pragma unroll
                for (int np = 0; np < 16; np++) {
                    uint32_t bh[4];
                    ldsm4t(bh, vrow + ((((np << 1) + cselV) ^ i7) << 4));
                    mma16816(Y[2 * np],     Ph, bh + 0);
                    mma16816(Y[2 * np + 1], Ph, bh + 2);
                }
            }
        }
    }

    // ---- single row-sum reduction at the end ----
    rl += __shfl_xor_sync(0xffffffffu, rl, 1);
    rl += __shfl_xor_sync(0xffffffffu, rl, 2);
    rh += __shfl_xor_sync(0xffffffffu, rh, 1);
    rh += __shfl_xor_sync(0xffffffffu, rh, 2);

    // ---- epilogue: y = (csum + Ydot) / l ----
    const float il = 1.0f / rl;
    const float ih = 1.0f / rh;
    const int rlo = qb * 128 + q0 + g;
    const float* cs_base = g_csum + b * DIM + z * 256 + 2 * tg;
    float* o_lo = out + ((size_t)b * SEQ + rlo) * DIM + (size_t)z * 256 + 2 * tg;
    float* o_hi = o_lo + (size_t)8 * DIM;
#pragma unroll
    for (int n = 0; n < 32; n++) {
        float2 cs = *(const float2*)(cs_base + 8 * n);
        float2 p;
        p.x = (Y[n][0] + cs.x) * il; p.y = (Y[n][1] + cs.y) * il;
        *(float2*)(o_lo + 8 * n) = p;
        p.x = (Y[n][2] + cs.x) * ih; p.y = (Y[n][3] + cs.y) * ih;
        *(float2*)(o_hi + 8 * n) = p;
    }
}

// ---------------------------------------------------------------------------
extern "C" void kernel_launch(void* const* d_in, const int* in_sizes, int n_in,
                              void* d_out, int out_size) {
    const float* x = (const float*)d_in[0];
    const float* Q = (const float*)d_in[1];
    float* out = (float*)d_out;

    cudaFuncSetAttribute(attn_kernel, cudaFuncAttributeMaxDynamicSharedMemorySize,
                         SMEM_TOTAL);
    cudaFuncSetAttribute(projH_kernel, cudaFuncAttributeMaxDynamicSharedMemorySize,
                         PSM_TOTAL);

    cvtsum_kernel<<<dim3(SEQ / 128, BATCH), 256>>>(x);
    qprep_kernel<<<DIM / 64, 256>>>(Q);
    projH_kernel<<<BATCH * SEQ / 128, 256, PSM_TOTAL>>>();
    csum2_kernel<<<BATCH * DIM / 256, 256>>>();
    attn_kernel<<<dim3(SEQ / 128, DIM / 256, BATCH), 256, SMEM_TOTAL>>>(out);
}